// round 14
// baseline (speedup 1.0000x reference)
#include <cuda_runtime.h>
#include <math.h>

// Problem constants
#define NB 32          // batch
#define CC 256         // channels
#define HW 4096        // H*W
#define GG 4           // groups
#define DD 64          // channels per group
#define MMTOT 131072   // m = NB*HW
#define CHUNKS 4       // hw chunks per (n,g)
#define TK 1024        // hw per chunk
#define SUB 64         // k-subtile
#define NSUB 16        // TK/SUB
#define LDA 68         // smem stride, gram tile
#define LDB 72         // smem stride, apply tile (bank = 8*k + n : conflict-free)

// XOR swizzle for the 64-stride NS matrices
#define SW(r,c) (((r) << 6) + ((c) ^ (((r) & 7) << 2)))

// Scratch (device globals; no allocation allowed)
__device__ float g_s1p[CHUNKS*NB*CC];   // per-chunk partial sums (no atomics)
__device__ float g_s2p[CHUNKS*NB*CC];
__device__ float g_gram[GG*DD*DD];
__device__ float g_pw[GG*DD*DD];        // w * P per group
__device__ float g_y[NB*CC];            // sigmoid MLP output
__device__ float g_varsum;              // sum of x_var over all (n,c)

// ---------------------------------------------------------------------------
__device__ __forceinline__ unsigned f2tf(float x) {
    unsigned r; asm("cvt.rna.tf32.f32 %0, %1;" : "=r"(r) : "f"(x)); return r;
}
__device__ __forceinline__ float f2tff(float x) {
    unsigned r; asm("cvt.rna.tf32.f32 %0, %1;" : "=r"(r) : "f"(x));
    return __uint_as_float(r);
}

// m16n8k8 tf32 mma, accumulate in-place.
__device__ __forceinline__ void mma8(float c[4],
        unsigned a0, unsigned a1, unsigned a2, unsigned a3,
        unsigned b0, unsigned b1) {
    asm("mma.sync.aligned.m16n8k8.row.col.f32.tf32.tf32.f32 "
        "{%0,%1,%2,%3}, {%4,%5,%6,%7}, {%8,%9}, {%0,%1,%2,%3};"
        : "+f"(c[0]), "+f"(c[1]), "+f"(c[2]), "+f"(c[3])
        : "r"(a0), "r"(a1), "r"(a2), "r"(a3), "r"(b0), "r"(b1));
}

// ---------------------------------------------------------------------------
__global__ void k_zero() {
    int i = blockIdx.x * blockDim.x + threadIdx.x;
    if (i < GG*DD*DD) g_gram[i] = 0.f;
    if (i == 0) g_varsum = 0.f;
}

// ---------------------------------------------------------------------------
// Pass 1: read X once. Per-(n,c) partial sum & sumsq + per-group Gram
// (hi*hi^T). smem tile holds tf32-pre-rounded values; fragment loads are
// paired LDS.64 via k-permutation (same relabel on A and B => dot product
// preserved). Grid: (CHUNKS, GG, NB), 256 threads.
__global__ __launch_bounds__(256, 3) void k_statsgram(const float* __restrict__ X) {
    __shared__ float As[DD*LDA];
    int n = blockIdx.z, g = blockIdx.y, chn = blockIdx.x;
    const float* base = X + ((size_t)(n*CC + g*DD))*HW + (size_t)chn*TK;
    int t = threadIdx.x, lane = t & 31, w = t >> 5;
    int gid = lane >> 2, tig = lane & 3;
    int m0 = (w & 3) << 4;      // warp row tile (16)
    int n0 = (w >> 2) << 5;     // warp col tile (32)

    float acc[4][4];
    #pragma unroll
    for (int j = 0; j < 4; j++)
        #pragma unroll
        for (int q = 0; q < 4; q++) acc[j][q] = 0.f;
    float s1[4] = {0.f,0.f,0.f,0.f}, s2[4] = {0.f,0.f,0.f,0.f};

    // prefetch subtile 0
    float4 v[4];
    #pragma unroll
    for (int i = 0; i < 4; i++) {
        int idx = t + (i << 8);
        int c = idx >> 4, k4 = (idx & 15) << 2;
        v[i] = *(const float4*)(base + (size_t)c*HW + k4);
    }

    for (int sub = 0; sub < NSUB; sub++) {
        if (sub) __syncthreads();
        #pragma unroll
        for (int i = 0; i < 4; i++) {
            int idx = t + (i << 8);
            int c = idx >> 4, k4 = (idx & 15) << 2;
            s1[i] += v[i].x + v[i].y + v[i].z + v[i].w;
            s2[i] += v[i].x*v[i].x + v[i].y*v[i].y + v[i].z*v[i].z + v[i].w*v[i].w;
            float4 h = make_float4(f2tff(v[i].x), f2tff(v[i].y),
                                   f2tff(v[i].z), f2tff(v[i].w));
            *(float4*)&As[c*LDA + k4] = h;
        }
        __syncthreads();
        if (sub + 1 < NSUB) {
            #pragma unroll
            for (int i = 0; i < 4; i++) {
                int idx = t + (i << 8);
                int c = idx >> 4, k4 = (idx & 15) << 2;
                v[i] = *(const float4*)(base + (size_t)c*HW + (sub+1)*SUB + k4);
            }
        }

        #pragma unroll
        for (int k0 = 0; k0 < SUB; k0 += 8) {
            // k-relabel: phys {k0+2t, k0+2t+1} -> logical {t, t+4} (A & B alike)
            int ra = (m0 + gid)*LDA + k0 + 2*tig;
            float2 aA = *(const float2*)&As[ra];           // (a0, a2)
            float2 aB = *(const float2*)&As[ra + 8*LDA];   // (a1, a3)
            #pragma unroll
            for (int j = 0; j < 4; j++) {
                int rb = (n0 + 8*j + gid)*LDA + k0 + 2*tig;
                float2 bb = *(const float2*)&As[rb];       // (b0, b1)
                mma8(acc[j],
                     __float_as_uint(aA.x), __float_as_uint(aB.x),
                     __float_as_uint(aA.y), __float_as_uint(aB.y),
                     __float_as_uint(bb.x), __float_as_uint(bb.y));
            }
        }
    }

    // per-channel stats: 16 threads share channel c = (t>>4) + 16*i
    #pragma unroll
    for (int i = 0; i < 4; i++) {
        float a = s1[i], b = s2[i];
        #pragma unroll
        for (int off = 8; off >= 1; off >>= 1) {
            a += __shfl_xor_sync(0xffffffffu, a, off, 16);
            b += __shfl_xor_sync(0xffffffffu, b, off, 16);
        }
        if ((t & 15) == 0) {
            int c = (t >> 4) + (i << 4);
            int o = chn*NB*CC + n*CC + g*DD + c;
            g_s1p[o] = a;
            g_s2p[o] = b;
        }
    }
    // Gram accumulation
    float* gg = &g_gram[g*DD*DD];
    #pragma unroll
    for (int j = 0; j < 4; j++) {
        int col = n0 + 8*j + 2*tig;
        atomicAdd(&gg[(m0+gid)*DD   + col],     acc[j][0]);
        atomicAdd(&gg[(m0+gid)*DD   + col + 1], acc[j][1]);
        atomicAdd(&gg[(m0+gid+8)*DD + col],     acc[j][2]);
        atomicAdd(&gg[(m0+gid+8)*DD + col + 1], acc[j][3]);
    }
}

// ---------------------------------------------------------------------------
// Fused middle kernel: blocks 0..NB-1 run the per-n MLP; blocks NB..NB+GG-1
// run Sigma_N + Newton-Schulz (iteration 1 done in closed form).
__device__ __forceinline__ void mm_tc(float c[4][4], const float* __restrict__ A,
                                      const float* __restrict__ B,
                                      int m0, int n0, int gid, int tig) {
    #pragma unroll
    for (int j = 0; j < 4; j++)
        #pragma unroll
        for (int q = 0; q < 4; q++) c[j][q] = 0.f;
    #pragma unroll
    for (int k0 = 0; k0 < DD; k0 += 8) {
        float a0r = A[SW(m0+gid,   k0+tig)];
        float a1r = A[SW(m0+gid+8, k0+tig)];
        float a2r = A[SW(m0+gid,   k0+tig+4)];
        float a3r = A[SW(m0+gid+8, k0+tig+4)];
        unsigned ah0 = f2tf(a0r), ah1 = f2tf(a1r), ah2 = f2tf(a2r), ah3 = f2tf(a3r);
        unsigned al0 = __float_as_uint(a0r - __uint_as_float(ah0));
        unsigned al1 = __float_as_uint(a1r - __uint_as_float(ah1));
        unsigned al2 = __float_as_uint(a2r - __uint_as_float(ah2));
        unsigned al3 = __float_as_uint(a3r - __uint_as_float(ah3));
        #pragma unroll
        for (int j = 0; j < 4; j++) {
            unsigned bh0 = f2tf(B[SW(k0+tig,   n0+8*j+gid)]);
            unsigned bh1 = f2tf(B[SW(k0+tig+4, n0+8*j+gid)]);
            mma8(c[j], ah0, ah1, ah2, ah3, bh0, bh1);  // hi*hi
            mma8(c[j], al0, al1, al2, al3, bh0, bh1);  // lo*hi
        }
    }
}

__device__ __forceinline__ void st_tile(float* __restrict__ D, const float c[4][4],
                                        int m0, int n0, int gid, int tig) {
    #pragma unroll
    for (int j = 0; j < 4; j++) {
        int col = n0 + 8*j + 2*tig;
        D[SW(m0+gid,   col)]     = c[j][0];
        D[SW(m0+gid,   col + 1)] = c[j][1];
        D[SW(m0+gid+8, col)]     = c[j][2];
        D[SW(m0+gid+8, col + 1)] = c[j][3];
    }
}

__global__ __launch_bounds__(256) void k_mid(const float* __restrict__ fc1,
                                             const float* __restrict__ lng,
                                             const float* __restrict__ lnb,
                                             const float* __restrict__ fc2,
                                             const float* __restrict__ xw) {
    __shared__ float sbuf[3*DD*DD + DD + 8 + 4];
    int t = threadIdx.x;

    if (blockIdx.x < NB) {
        // ================= reweight MLP =================
        float* sv      = sbuf;            // 256
        float* sh      = sbuf + 256;      // 64
        float* warpsum = sbuf + 320;      // 8
        float* sred    = sbuf + 328;      // 2
        int n = blockIdx.x;

        float s  = 0.f, ss = 0.f;
        #pragma unroll
        for (int ch = 0; ch < CHUNKS; ch++) {
            s  += g_s1p[ch*NB*CC + n*CC + t];
            ss += g_s2p[ch*NB*CC + n*CC + t];
        }
        float var = (ss - s*s*(1.0f/HW)) * (1.0f/(HW - 1));   // ddof=1
        sv[t] = var;

        float vs = var;
        #pragma unroll
        for (int o = 16; o; o >>= 1) vs += __shfl_xor_sync(0xffffffffu, vs, o);
        if ((t & 31) == 0) warpsum[t >> 5] = vs;
        __syncthreads();
        if (t == 0) {
            float tot = 0.f;
            #pragma unroll
            for (int i = 0; i < 8; i++) tot += warpsum[i];
            atomicAdd(&g_varsum, tot);
        }

        int w = t >> 5, l = t & 31;
        for (int kk = 0; kk < 8; kk++) {
            int k = w*8 + kk;
            float acc = 0.f;
            for (int c = l; c < CC; c += 32) acc += sv[c] * fc1[k*CC + c];
            #pragma unroll
            for (int o = 16; o; o >>= 1) acc += __shfl_xor_sync(0xffffffffu, acc, o);
            if (l == 0) sh[k] = acc;
        }
        __syncthreads();

        if (w == 0) {
            float h1 = sh[l], h2 = sh[l + 32];
            float su = h1 + h2, q = h1*h1 + h2*h2;
            #pragma unroll
            for (int o = 16; o; o >>= 1) {
                su += __shfl_xor_sync(0xffffffffu, su, o);
                q  += __shfl_xor_sync(0xffffffffu, q,  o);
            }
            float mu = su * (1.0f/DD);
            float vr = q * (1.0f/DD) - mu*mu;
            if (l == 0) { sred[0] = mu; sred[1] = rsqrtf(vr + 1e-5f); }
        }
        __syncthreads();
        float mu = sred[0], rstd = sred[1];
        if (t < DD) {
            float hh = (sh[t] - mu) * rstd * lng[t] + lnb[t];
            sh[t] = fmaxf(hh, 0.f);
        }
        __syncthreads();

        float acc = 0.f;
        #pragma unroll 8
        for (int k = 0; k < DD; k++) acc += sh[k] * fc2[t*DD + k];
        g_y[n*CC + t] = 1.0f / (1.0f + expf(-acc));
    } else {
        // ================= Sigma_N + Newton-Schulz =================
        float* sP     = sbuf;
        float* sS     = sbuf + DD*DD;
        float* sT     = sbuf + 2*DD*DD;
        float* smean  = sbuf + 3*DD*DD;
        float* strace = sbuf + 3*DD*DD + DD;
        int g = blockIdx.x - NB;
        int lane = t & 31, w = t >> 5;
        int gid = lane >> 2, tig = lane & 3;
        int m0 = (w & 3) << 4;
        int n0 = (w >> 2) << 5;

        if (t < DD) {
            float s = 0.f;
            #pragma unroll 4
            for (int n = 0; n < NB; n++)
                #pragma unroll
                for (int ch = 0; ch < CHUNKS; ch++)
                    s += g_s1p[ch*NB*CC + n*CC + g*DD + t];
            smean[t] = s * (1.0f/(float)MMTOT);
        }
        if (t == 0) strace[0] = 0.f;
        __syncthreads();
        float tr = 0.f;
        #pragma unroll
        for (int i = 0; i < 16; i++) {
            int idx = t + i*256;
            int r = idx >> 6, c = idx & 63;
            float vv = 1e-5f * (g_gram[g*DD*DD + idx] - (float)MMTOT * smean[r] * smean[c]);
            if (r == c) { vv += 1.0f/(float)MMTOT; tr += vv; }
            sS[SW(r,c)] = vv;
        }
        #pragma unroll
        for (int o = 16; o; o >>= 1) tr += __shfl_xor_sync(0xffffffffu, tr, o);
        if ((t & 31) == 0) atomicAdd(strace, tr);
        __syncthreads();
        float rtr = 1.0f / strace[0];
        // Scale Sn and do NS iteration 1 in closed form: P1 = -0.5 I + 1.5 Sn
        #pragma unroll
        for (int i = 0; i < 16; i++) {
            int idx = t + i*256;
            int r = idx >> 6, c = idx & 63;
            float sv_ = sS[SW(r,c)] * rtr;
            sS[SW(r,c)] = sv_;
            sP[SW(r,c)] = ((r == c) ? -0.5f : 0.0f) + 1.5f*sv_;
        }
        __syncthreads();

        // NS iterations 2..3
        for (int it = 0; it < 2; it++) {
            float cr[4][4];
            mm_tc(cr, sP, sP, m0, n0, gid, tig);     // T = P@P
            st_tile(sT, cr, m0, n0, gid, tig);
            __syncthreads();

            mm_tc(cr, sT, sP, m0, n0, gid, tig);     // P3 = T@P (regs)
            float pold[4][4];
            #pragma unroll
            for (int j = 0; j < 4; j++) {
                int col = n0 + 8*j + 2*tig;
                pold[j][0] = sP[SW(m0+gid,   col)];
                pold[j][1] = sP[SW(m0+gid,   col+1)];
                pold[j][2] = sP[SW(m0+gid+8, col)];
                pold[j][3] = sP[SW(m0+gid+8, col+1)];
            }
            __syncthreads();
            st_tile(sT, cr, m0, n0, gid, tig);       // sT <- P3
            __syncthreads();

            mm_tc(cr, sT, sS, m0, n0, gid, tig);     // F = P3@S
            #pragma unroll
            for (int j = 0; j < 4; j++)
                #pragma unroll
                for (int q = 0; q < 4; q++)
                    cr[j][q] = -0.5f*pold[j][q] + 1.5f*cr[j][q];
            st_tile(sP, cr, m0, n0, gid, tig);       // P <- update
            __syncthreads();
        }

        float wb = 1.0f / (1.0f + expf(-xw[0]));
        #pragma unroll
        for (int i = 0; i < 16; i++) {
            int idx = t + i*256;
            int r = idx >> 6, c = idx & 63;
            g_pw[g*DD*DD + idx] = wb * sP[SW(r,c)];
        }
    }
}

// ---------------------------------------------------------------------------
// Pass 2: out = (wP + diag(coef)) @ X, single fused mma product. A-fragments
// (incl. folded residual diagonal) preloaded in registers; smem holds tf32-
// pre-rounded X; inner loop pure LDS+mma; epilogue pure STG from accumulators.
// Grid: (CHUNKS, GG, NB), 256 threads.
__global__ __launch_bounds__(256, 3) void k_apply(const float* __restrict__ X,
                                                  const float* __restrict__ xw,
                                                  float* __restrict__ out) {
    __shared__ float Xs[DD*LDB];
    int n = blockIdx.z, g = blockIdx.y, chn = blockIdx.x;
    const float* base = X   + ((size_t)(n*CC + g*DD))*HW + (size_t)chn*TK;
    float*      obase = out + ((size_t)(n*CC + g*DD))*HW + (size_t)chn*TK;
    int t = threadIdx.x, lane = t & 31, w = t >> 5;
    int gid = lane >> 2, tig = lane & 3;
    int m0 = (w & 3) << 4;
    int nw0 = (w >> 2) << 5;

    float wblend = 1.0f / (1.0f + expf(-xw[0]));
    float rscale = rsqrtf(g_varsum * (1.0f/(float)(NB*CC)));
    float coef0 = (1.0f - wblend) * g_y[n*CC + g*DD + m0 + gid]     * rscale;
    float coef1 = (1.0f - wblend) * g_y[n*CC + g*DD + m0 + gid + 8] * rscale;

    // preload A = wP + diag(coef) as tf32 fragments (rows m0+gid/+8, k-tiles 0..7)
    unsigned pah[8][4];
    const float* P = &g_pw[g*DD*DD];
    #pragma unroll
    for (int kt = 0; kt < 8; kt++) {
        int k0 = kt*8;
        float a0 = P[(m0+gid)*DD   + k0 + tig];
        float a1 = P[(m0+gid+8)*DD + k0 + tig];
        float a2 = P[(m0+gid)*DD   + k0 + tig + 4];
        float a3 = P[(m0+gid+8)*DD + k0 + tig + 4];
        if (m0+gid   == k0 + tig)     a0 += coef0;
        if (m0+gid+8 == k0 + tig)     a1 += coef1;
        if (m0+gid   == k0 + tig + 4) a2 += coef0;
        if (m0+gid+8 == k0 + tig + 4) a3 += coef1;
        pah[kt][0] = f2tf(a0);
        pah[kt][1] = f2tf(a1);
        pah[kt][2] = f2tf(a2);
        pah[kt][3] = f2tf(a3);
    }

    // prefetch subtile 0
    float4 v[4];
    #pragma unroll
    for (int i = 0; i < 4; i++) {
        int idx = t + (i << 8);
        int c = idx >> 4, k4 = (idx & 15) << 2;
        v[i] = *(const float4*)(base + (size_t)c*HW + k4);
    }

    for (int sub = 0; sub < NSUB; sub++) {
        if (sub) __syncthreads();
        #pragma unroll
        for (int i = 0; i < 4; i++) {
            int idx = t + (i << 8);
            int c = idx >> 4, k4 = (idx & 15) << 2;
            float4 h = make_float4(f2tff(v[i].x), f2tff(v[i].y),
                                   f2tff(v[i].z), f2tff(v[i].w));
            *(float4*)&Xs[c*LDB + k4] = h;
        }
        __syncthreads();
        if (sub + 1 < NSUB) {
            #pragma unroll
            for (int i = 0; i < 4; i++) {
                int idx = t + (i << 8);
                int c = idx >> 4, k4 = (idx & 15) << 2;
                v[i] = *(const float4*)(base + (size_t)c*HW + (sub+1)*SUB + k4);
            }
        }

        float acc[4][4];
        #pragma unroll
        for (int j = 0; j < 4; j++)
            #pragma unroll
            for (int q = 0; q < 4; q++) acc[j][q] = 0.f;

        #pragma unroll
        for (int kt = 0; kt < 8; kt++) {
            int k0 = kt*8;
            #pragma unroll
            for (int j = 0; j < 4; j++) {
                int rb = (k0 + tig)*LDB + nw0 + 8*j + gid;
                unsigned bh0 = __float_as_uint(Xs[rb]);
                unsigned bh1 = __float_as_uint(Xs[rb + 4*LDB]);
                mma8(acc[j], pah[kt][0], pah[kt][1], pah[kt][2], pah[kt][3], bh0, bh1);
            }
        }

        // epilogue: pure stores (residual already folded into A's diagonal)
        #pragma unroll
        for (int j = 0; j < 4; j++) {
            int col = nw0 + 8*j + 2*tig;
            int r1 = m0 + gid, r2 = r1 + 8;
            *(float2*)(obase + (size_t)r1*HW + sub*SUB + col) =
                make_float2(acc[j][0], acc[j][1]);
            *(float2*)(obase + (size_t)r2*HW + sub*SUB + col) =
                make_float2(acc[j][2], acc[j][3]);
        }
    }
}

// ---------------------------------------------------------------------------
extern "C" void kernel_launch(void* const* d_in, const int* in_sizes, int n_in,
                              void* d_out, int out_size) {
    const float* X   = (const float*)d_in[0];
    const float* fc1 = (const float*)d_in[1];
    const float* lng = (const float*)d_in[2];
    const float* lnb = (const float*)d_in[3];
    const float* fc2 = (const float*)d_in[4];
    const float* xw  = (const float*)d_in[5];
    float* out = (float*)d_out;

    k_zero<<<64, 256>>>();
    dim3 grid(CHUNKS, GG, NB);
    k_statsgram<<<grid, 256>>>(X);
    k_mid<<<NB + GG, 256>>>(fc1, lng, lnb, fc2, xw);
    k_apply<<<grid, 256>>>(X, xw, out);
}

// round 15
// speedup vs baseline: 1.2349x; 1.2349x over previous
#include <cuda_runtime.h>
#include <math.h>

// Problem constants
#define NB 32          // batch
#define CC 256         // channels
#define HW 4096        // H*W
#define GG 4           // groups
#define DD 64          // channels per group
#define MMTOT 131072   // m = NB*HW
#define CHUNKS 4       // hw chunks per (n,g)
#define TK 1024        // hw per chunk
#define SUB 64         // k-subtile
#define NSUB 16        // TK/SUB
#define LDA 68         // smem stride, gram tile  (bank = 4*gid + tig : conflict-free)
#define LDB 72         // smem stride, apply tile (bank = 8*tig + gid : conflict-free)

// XOR swizzle for the 64-stride NS matrices
#define SW(r,c) (((r) << 6) + ((c) ^ (((r) & 7) << 2)))

// Scratch (device globals; no allocation allowed)
__device__ float g_s1p[CHUNKS*NB*CC];   // per-chunk partial sums (no atomics)
__device__ float g_s2p[CHUNKS*NB*CC];
__device__ float g_gram[GG*DD*DD];
__device__ float g_pw[GG*DD*DD];        // w * P per group
__device__ float g_y[NB*CC];            // sigmoid MLP output
__device__ float g_varsum;              // sum of x_var over all (n,c)

// ---------------------------------------------------------------------------
__device__ __forceinline__ unsigned f2tf(float x) {
    unsigned r; asm("cvt.rna.tf32.f32 %0, %1;" : "=r"(r) : "f"(x)); return r;
}
__device__ __forceinline__ float f2tff(float x) {
    unsigned r; asm("cvt.rna.tf32.f32 %0, %1;" : "=r"(r) : "f"(x));
    return __uint_as_float(r);
}

// m16n8k8 tf32 mma, accumulate in-place.
__device__ __forceinline__ void mma8(float c[4],
        unsigned a0, unsigned a1, unsigned a2, unsigned a3,
        unsigned b0, unsigned b1) {
    asm("mma.sync.aligned.m16n8k8.row.col.f32.tf32.tf32.f32 "
        "{%0,%1,%2,%3}, {%4,%5,%6,%7}, {%8,%9}, {%0,%1,%2,%3};"
        : "+f"(c[0]), "+f"(c[1]), "+f"(c[2]), "+f"(c[3])
        : "r"(a0), "r"(a1), "r"(a2), "r"(a3), "r"(b0), "r"(b1));
}

// ---------------------------------------------------------------------------
__global__ void k_zero() {
    int i = blockIdx.x * blockDim.x + threadIdx.x;
    if (i < GG*DD*DD) g_gram[i] = 0.f;
    if (i == 0) g_varsum = 0.f;
}

// ---------------------------------------------------------------------------
// Pass 1: read X once. Per-(n,c) partial sum & sumsq + per-group Gram
// (hi*hi^T, tensor cores). Conflict-free LDS.32 fragment loads. Symmetry:
// warp tiles entirely below the diagonal (w=2,3) skip their mma loop; the
// mirrored tiles (w=4,5) write transposed copies in the epilogue.
// Grid: (CHUNKS, GG, NB), 256 threads.
__global__ __launch_bounds__(256, 3) void k_statsgram(const float* __restrict__ X) {
    __shared__ float As[DD*LDA];
    int n = blockIdx.z, g = blockIdx.y, chn = blockIdx.x;
    const float* base = X + ((size_t)(n*CC + g*DD))*HW + (size_t)chn*TK;
    int t = threadIdx.x, lane = t & 31, w = t >> 5;
    int gid = lane >> 2, tig = lane & 3;
    int m0 = (w & 3) << 4;      // warp row tile (16)
    int n0 = (w >> 2) << 5;     // warp col tile (32)
    bool skip   = (m0 >= n0 + 32);          // w = 2,3 : below-diagonal tiles
    bool mirror = (m0 < 32) && (n0 == 32);  // w = 4,5 : provide the mirrors

    float acc[4][4];
    #pragma unroll
    for (int j = 0; j < 4; j++)
        #pragma unroll
        for (int q = 0; q < 4; q++) acc[j][q] = 0.f;
    float s1[4] = {0.f,0.f,0.f,0.f}, s2[4] = {0.f,0.f,0.f,0.f};

    // prefetch subtile 0
    float4 v[4];
    #pragma unroll
    for (int i = 0; i < 4; i++) {
        int idx = t + (i << 8);
        int c = idx >> 4, k4 = (idx & 15) << 2;
        v[i] = *(const float4*)(base + (size_t)c*HW + k4);
    }

    for (int sub = 0; sub < NSUB; sub++) {
        if (sub) __syncthreads();
        #pragma unroll
        for (int i = 0; i < 4; i++) {
            int idx = t + (i << 8);
            int c = idx >> 4, k4 = (idx & 15) << 2;
            s1[i] += v[i].x + v[i].y + v[i].z + v[i].w;
            s2[i] += v[i].x*v[i].x + v[i].y*v[i].y + v[i].z*v[i].z + v[i].w*v[i].w;
            float4 h = make_float4(f2tff(v[i].x), f2tff(v[i].y),
                                   f2tff(v[i].z), f2tff(v[i].w));
            *(float4*)&As[c*LDA + k4] = h;
        }
        __syncthreads();
        if (sub + 1 < NSUB) {
            #pragma unroll
            for (int i = 0; i < 4; i++) {
                int idx = t + (i << 8);
                int c = idx >> 4, k4 = (idx & 15) << 2;
                v[i] = *(const float4*)(base + (size_t)c*HW + (sub+1)*SUB + k4);
            }
        }

        if (!skip) {
            #pragma unroll
            for (int k0 = 0; k0 < SUB; k0 += 8) {
                int ra = (m0 + gid)*LDA + k0 + tig;
                unsigned ah0 = __float_as_uint(As[ra]);
                unsigned ah1 = __float_as_uint(As[ra + 8*LDA]);
                unsigned ah2 = __float_as_uint(As[ra + 4]);
                unsigned ah3 = __float_as_uint(As[ra + 8*LDA + 4]);
                #pragma unroll
                for (int j = 0; j < 4; j++) {
                    int rb = (n0 + 8*j + gid)*LDA + k0 + tig;
                    unsigned bh0 = __float_as_uint(As[rb]);
                    unsigned bh1 = __float_as_uint(As[rb + 4]);
                    mma8(acc[j], ah0, ah1, ah2, ah3, bh0, bh1);
                }
            }
        }
    }

    // per-channel stats: 16 threads share channel c = (t>>4) + 16*i
    #pragma unroll
    for (int i = 0; i < 4; i++) {
        float a = s1[i], b = s2[i];
        #pragma unroll
        for (int off = 8; off >= 1; off >>= 1) {
            a += __shfl_xor_sync(0xffffffffu, a, off, 16);
            b += __shfl_xor_sync(0xffffffffu, b, off, 16);
        }
        if ((t & 15) == 0) {
            int c = (t >> 4) + (i << 4);
            int o = chn*NB*CC + n*CC + g*DD + c;
            g_s1p[o] = a;
            g_s2p[o] = b;
        }
    }
    // Gram accumulation (+ transposed mirror for the skipped tiles)
    if (!skip) {
        float* gg = &g_gram[g*DD*DD];
        #pragma unroll
        for (int j = 0; j < 4; j++) {
            int col = n0 + 8*j + 2*tig;
            int r1 = m0 + gid, r2 = r1 + 8;
            atomicAdd(&gg[r1*DD + col],     acc[j][0]);
            atomicAdd(&gg[r1*DD + col + 1], acc[j][1]);
            atomicAdd(&gg[r2*DD + col],     acc[j][2]);
            atomicAdd(&gg[r2*DD + col + 1], acc[j][3]);
            if (mirror) {
                atomicAdd(&gg[col*DD     + r1], acc[j][0]);
                atomicAdd(&gg[(col+1)*DD + r1], acc[j][1]);
                atomicAdd(&gg[col*DD     + r2], acc[j][2]);
                atomicAdd(&gg[(col+1)*DD + r2], acc[j][3]);
            }
        }
    }
}

// ---------------------------------------------------------------------------
// Fused middle kernel: blocks 0..NB-1 run the per-n MLP; blocks NB..NB+GG-1
// run Sigma_N + Newton-Schulz (iteration 1 closed-form).
__device__ __forceinline__ void mm_tc(float c[4][4], const float* __restrict__ A,
                                      const float* __restrict__ B,
                                      int m0, int n0, int gid, int tig) {
    #pragma unroll
    for (int j = 0; j < 4; j++)
        #pragma unroll
        for (int q = 0; q < 4; q++) c[j][q] = 0.f;
    #pragma unroll
    for (int k0 = 0; k0 < DD; k0 += 8) {
        float a0r = A[SW(m0+gid,   k0+tig)];
        float a1r = A[SW(m0+gid+8, k0+tig)];
        float a2r = A[SW(m0+gid,   k0+tig+4)];
        float a3r = A[SW(m0+gid+8, k0+tig+4)];
        unsigned ah0 = f2tf(a0r), ah1 = f2tf(a1r), ah2 = f2tf(a2r), ah3 = f2tf(a3r);
        unsigned al0 = __float_as_uint(a0r - __uint_as_float(ah0));
        unsigned al1 = __float_as_uint(a1r - __uint_as_float(ah1));
        unsigned al2 = __float_as_uint(a2r - __uint_as_float(ah2));
        unsigned al3 = __float_as_uint(a3r - __uint_as_float(ah3));
        #pragma unroll
        for (int j = 0; j < 4; j++) {
            unsigned bh0 = f2tf(B[SW(k0+tig,   n0+8*j+gid)]);
            unsigned bh1 = f2tf(B[SW(k0+tig+4, n0+8*j+gid)]);
            mma8(c[j], ah0, ah1, ah2, ah3, bh0, bh1);  // hi*hi
            mma8(c[j], al0, al1, al2, al3, bh0, bh1);  // lo*hi
        }
    }
}

__device__ __forceinline__ void st_tile(float* __restrict__ D, const float c[4][4],
                                        int m0, int n0, int gid, int tig) {
    #pragma unroll
    for (int j = 0; j < 4; j++) {
        int col = n0 + 8*j + 2*tig;
        D[SW(m0+gid,   col)]     = c[j][0];
        D[SW(m0+gid,   col + 1)] = c[j][1];
        D[SW(m0+gid+8, col)]     = c[j][2];
        D[SW(m0+gid+8, col + 1)] = c[j][3];
    }
}

__global__ __launch_bounds__(256) void k_mid(const float* __restrict__ fc1,
                                             const float* __restrict__ lng,
                                             const float* __restrict__ lnb,
                                             const float* __restrict__ fc2,
                                             const float* __restrict__ xw) {
    __shared__ float sbuf[3*DD*DD + DD + 8 + 4];
    int t = threadIdx.x;

    if (blockIdx.x < NB) {
        // ================= reweight MLP =================
        float* sv      = sbuf;
        float* sh      = sbuf + 256;
        float* warpsum = sbuf + 320;
        float* sred    = sbuf + 328;
        int n = blockIdx.x;

        float s  = 0.f, ss = 0.f;
        #pragma unroll
        for (int ch = 0; ch < CHUNKS; ch++) {
            s  += g_s1p[ch*NB*CC + n*CC + t];
            ss += g_s2p[ch*NB*CC + n*CC + t];
        }
        float var = (ss - s*s*(1.0f/HW)) * (1.0f/(HW - 1));   // ddof=1
        sv[t] = var;

        float vs = var;
        #pragma unroll
        for (int o = 16; o; o >>= 1) vs += __shfl_xor_sync(0xffffffffu, vs, o);
        if ((t & 31) == 0) warpsum[t >> 5] = vs;
        __syncthreads();
        if (t == 0) {
            float tot = 0.f;
            #pragma unroll
            for (int i = 0; i < 8; i++) tot += warpsum[i];
            atomicAdd(&g_varsum, tot);
        }

        int w = t >> 5, l = t & 31;
        for (int kk = 0; kk < 8; kk++) {
            int k = w*8 + kk;
            float acc = 0.f;
            for (int c = l; c < CC; c += 32) acc += sv[c] * fc1[k*CC + c];
            #pragma unroll
            for (int o = 16; o; o >>= 1) acc += __shfl_xor_sync(0xffffffffu, acc, o);
            if (l == 0) sh[k] = acc;
        }
        __syncthreads();

        if (w == 0) {
            float h1 = sh[l], h2 = sh[l + 32];
            float su = h1 + h2, q = h1*h1 + h2*h2;
            #pragma unroll
            for (int o = 16; o; o >>= 1) {
                su += __shfl_xor_sync(0xffffffffu, su, o);
                q  += __shfl_xor_sync(0xffffffffu, q,  o);
            }
            float mu = su * (1.0f/DD);
            float vr = q * (1.0f/DD) - mu*mu;
            if (l == 0) { sred[0] = mu; sred[1] = rsqrtf(vr + 1e-5f); }
        }
        __syncthreads();
        float mu = sred[0], rstd = sred[1];
        if (t < DD) {
            float hh = (sh[t] - mu) * rstd * lng[t] + lnb[t];
            sh[t] = fmaxf(hh, 0.f);
        }
        __syncthreads();

        float acc = 0.f;
        #pragma unroll 8
        for (int k = 0; k < DD; k++) acc += sh[k] * fc2[t*DD + k];
        g_y[n*CC + t] = 1.0f / (1.0f + expf(-acc));
    } else {
        // ================= Sigma_N + Newton-Schulz =================
        float* sP     = sbuf;
        float* sS     = sbuf + DD*DD;
        float* sT     = sbuf + 2*DD*DD;
        float* smean  = sbuf + 3*DD*DD;
        float* strace = sbuf + 3*DD*DD + DD;
        int g = blockIdx.x - NB;
        int lane = t & 31, w = t >> 5;
        int gid = lane >> 2, tig = lane & 3;
        int m0 = (w & 3) << 4;
        int n0 = (w >> 2) << 5;

        if (t < DD) {
            float s = 0.f;
            #pragma unroll 4
            for (int n = 0; n < NB; n++)
                #pragma unroll
                for (int ch = 0; ch < CHUNKS; ch++)
                    s += g_s1p[ch*NB*CC + n*CC + g*DD + t];
            smean[t] = s * (1.0f/(float)MMTOT);
        }
        if (t == 0) strace[0] = 0.f;
        __syncthreads();
        float tr = 0.f;
        #pragma unroll
        for (int i = 0; i < 16; i++) {
            int idx = t + i*256;
            int r = idx >> 6, c = idx & 63;
            float vv = 1e-5f * (g_gram[g*DD*DD + idx] - (float)MMTOT * smean[r] * smean[c]);
            if (r == c) { vv += 1.0f/(float)MMTOT; tr += vv; }
            sS[SW(r,c)] = vv;
        }
        #pragma unroll
        for (int o = 16; o; o >>= 1) tr += __shfl_xor_sync(0xffffffffu, tr, o);
        if ((t & 31) == 0) atomicAdd(strace, tr);
        __syncthreads();
        float rtr = 1.0f / strace[0];
        // Scale Sn; NS iteration 1 closed-form: P1 = -0.5 I + 1.5 Sn
        #pragma unroll
        for (int i = 0; i < 16; i++) {
            int idx = t + i*256;
            int r = idx >> 6, c = idx & 63;
            float sv_ = sS[SW(r,c)] * rtr;
            sS[SW(r,c)] = sv_;
            sP[SW(r,c)] = ((r == c) ? -0.5f : 0.0f) + 1.5f*sv_;
        }
        __syncthreads();

        for (int it = 0; it < 2; it++) {
            float cr[4][4];
            mm_tc(cr, sP, sP, m0, n0, gid, tig);     // T = P@P
            st_tile(sT, cr, m0, n0, gid, tig);
            __syncthreads();

            mm_tc(cr, sT, sP, m0, n0, gid, tig);     // P3 = T@P (regs)
            float pold[4][4];
            #pragma unroll
            for (int j = 0; j < 4; j++) {
                int col = n0 + 8*j + 2*tig;
                pold[j][0] = sP[SW(m0+gid,   col)];
                pold[j][1] = sP[SW(m0+gid,   col+1)];
                pold[j][2] = sP[SW(m0+gid+8, col)];
                pold[j][3] = sP[SW(m0+gid+8, col+1)];
            }
            __syncthreads();
            st_tile(sT, cr, m0, n0, gid, tig);       // sT <- P3
            __syncthreads();

            mm_tc(cr, sT, sS, m0, n0, gid, tig);     // F = P3@S
            #pragma unroll
            for (int j = 0; j < 4; j++)
                #pragma unroll
                for (int q = 0; q < 4; q++)
                    cr[j][q] = -0.5f*pold[j][q] + 1.5f*cr[j][q];
            st_tile(sP, cr, m0, n0, gid, tig);       // P <- update
            __syncthreads();
        }

        float wb = 1.0f / (1.0f + expf(-xw[0]));
        #pragma unroll
        for (int i = 0; i < 16; i++) {
            int idx = t + i*256;
            int r = idx >> 6, c = idx & 63;
            g_pw[g*DD*DD + idx] = wb * sP[SW(r,c)];
        }
    }
}

// ---------------------------------------------------------------------------
// Pass 2: out = (wP + diag(coef)) @ X. Warp tile m32 x n16: P fragments for
// TWO m-tiles live in registers (A free), halving per-warp B smem traffic.
// smem holds tf32-pre-rounded X; inner loop pure LDS+mma; epilogue pure STG.
// Grid: (CHUNKS, GG, NB), 256 threads.
__global__ __launch_bounds__(256, 2) void k_apply(const float* __restrict__ X,
                                                  const float* __restrict__ xw,
                                                  float* __restrict__ out) {
    __shared__ float Xs[DD*LDB];
    int n = blockIdx.z, g = blockIdx.y, chn = blockIdx.x;
    const float* base = X   + ((size_t)(n*CC + g*DD))*HW + (size_t)chn*TK;
    float*      obase = out + ((size_t)(n*CC + g*DD))*HW + (size_t)chn*TK;
    int t = threadIdx.x, lane = t & 31, w = t >> 5;
    int gid = lane >> 2, tig = lane & 3;
    int m0  = (w & 1) << 5;     // {0, 32}
    int nw0 = (w >> 1) << 4;    // {0, 16, 32, 48}

    float wblend = 1.0f / (1.0f + expf(-xw[0]));
    float rscale = rsqrtf(g_varsum * (1.0f/(float)(NB*CC)));

    // preload A = wP + diag(coef) fragments for 2 m-tiles (rows m0+16mt+gid/+8)
    unsigned pah[2][8][4];
    const float* P = &g_pw[g*DD*DD];
    #pragma unroll
    for (int mt = 0; mt < 2; mt++) {
        int r1 = m0 + mt*16 + gid, r2 = r1 + 8;
        float c1 = (1.0f - wblend) * g_y[n*CC + g*DD + r1] * rscale;
        float c2 = (1.0f - wblend) * g_y[n*CC + g*DD + r2] * rscale;
        #pragma unroll
        for (int kt = 0; kt < 8; kt++) {
            int k0 = kt*8;
            float a0 = P[r1*DD + k0 + tig];
            float a1 = P[r2*DD + k0 + tig];
            float a2 = P[r1*DD + k0 + tig + 4];
            float a3 = P[r2*DD + k0 + tig + 4];
            if (r1 == k0 + tig)     a0 += c1;
            if (r2 == k0 + tig)     a1 += c2;
            if (r1 == k0 + tig + 4) a2 += c1;
            if (r2 == k0 + tig + 4) a3 += c2;
            pah[mt][kt][0] = f2tf(a0);
            pah[mt][kt][1] = f2tf(a1);
            pah[mt][kt][2] = f2tf(a2);
            pah[mt][kt][3] = f2tf(a3);
        }
    }

    // prefetch subtile 0
    float4 v[4];
    #pragma unroll
    for (int i = 0; i < 4; i++) {
        int idx = t + (i << 8);
        int c = idx >> 4, k4 = (idx & 15) << 2;
        v[i] = *(const float4*)(base + (size_t)c*HW + k4);
    }

    for (int sub = 0; sub < NSUB; sub++) {
        if (sub) __syncthreads();
        #pragma unroll
        for (int i = 0; i < 4; i++) {
            int idx = t + (i << 8);
            int c = idx >> 4, k4 = (idx & 15) << 2;
            float4 h = make_float4(f2tff(v[i].x), f2tff(v[i].y),
                                   f2tff(v[i].z), f2tff(v[i].w));
            *(float4*)&Xs[c*LDB + k4] = h;
        }
        __syncthreads();
        if (sub + 1 < NSUB) {
            #pragma unroll
            for (int i = 0; i < 4; i++) {
                int idx = t + (i << 8);
                int c = idx >> 4, k4 = (idx & 15) << 2;
                v[i] = *(const float4*)(base + (size_t)c*HW + (sub+1)*SUB + k4);
            }
        }

        float acc[2][2][4];
        #pragma unroll
        for (int mt = 0; mt < 2; mt++)
            #pragma unroll
            for (int j = 0; j < 2; j++)
                #pragma unroll
                for (int q = 0; q < 4; q++) acc[mt][j][q] = 0.f;

        #pragma unroll
        for (int kt = 0; kt < 8; kt++) {
            int k0 = kt*8;
            #pragma unroll
            for (int j = 0; j < 2; j++) {
                int rb = (k0 + tig)*LDB + nw0 + 8*j + gid;
                unsigned bh0 = __float_as_uint(Xs[rb]);
                unsigned bh1 = __float_as_uint(Xs[rb + 4*LDB]);
                #pragma unroll
                for (int mt = 0; mt < 2; mt++)
                    mma8(acc[mt][j], pah[mt][kt][0], pah[mt][kt][1],
                         pah[mt][kt][2], pah[mt][kt][3], bh0, bh1);
            }
        }

        // epilogue: pure stores (residual folded into A's diagonal)
        #pragma unroll
        for (int mt = 0; mt < 2; mt++)
            #pragma unroll
            for (int j = 0; j < 2; j++) {
                int col = nw0 + 8*j + 2*tig;
                int r1 = m0 + mt*16 + gid, r2 = r1 + 8;
                *(float2*)(obase + (size_t)r1*HW + sub*SUB + col) =
                    make_float2(acc[mt][j][0], acc[mt][j][1]);
                *(float2*)(obase + (size_t)r2*HW + sub*SUB + col) =
                    make_float2(acc[mt][j][2], acc[mt][j][3]);
            }
    }
}

// ---------------------------------------------------------------------------
extern "C" void kernel_launch(void* const* d_in, const int* in_sizes, int n_in,
                              void* d_out, int out_size) {
    const float* X   = (const float*)d_in[0];
    const float* fc1 = (const float*)d_in[1];
    const float* lng = (const float*)d_in[2];
    const float* lnb = (const float*)d_in[3];
    const float* fc2 = (const float*)d_in[4];
    const float* xw  = (const float*)d_in[5];
    float* out = (float*)d_out;

    k_zero<<<64, 256>>>();
    dim3 grid(CHUNKS, GG, NB);
    k_statsgram<<<grid, 256>>>(X);
    k_mid<<<NB + GG, 256>>>(fc1, lng, lnb, fc2, xw);
    k_apply<<<grid, 256>>>(X, xw, out);
}